// round 15
// baseline (speedup 1.0000x reference)
#include <cuda_runtime.h>
#include <cuda_bf16.h>
#include <math.h>

#define B_    32
#define EMB_  256
#define HID_  516
#define G4_   2064     // 4*HID_
#define V_    32000
#define ROWS_ 2048     // 64*32 decoder rows
#define NK_   528      // K padded to multiple of 16 (hist layout)
#define NKI_  33       // k-iterations of 16
#define SROW_ 536      // row stride (u16) for h/W tiles, ldmatrix conflict-free
#define XROW_ 264      // smem row stride (u16) for K=256 tiles
#define NPAD_ 2112     // gate-col dim padded (66 tiles * 32)
#define SCANB_ 132     // scan blocks (<=148, all co-resident)
#define CROW2_ 72      // CE A-chunk row stride (u16), 64 cols + pad
#define BUFB_  34304   // one staged buffer: 32*SROW_*2 bytes

// ---------------- scratch (static device globals; no allocation) ----------------
__device__ __nv_bfloat16 g_Wb[6][NPAD_ * SROW_];      // scan weights bf16, PADDED rows
__device__ float         g_pre[2][ROWS_ * G4_];       // input proj + bias, gate-interleaved
__device__ __nv_bfloat16 g_hb[2][2][B_ * SROW_];      // h state [layer][buf], PADDED rows
__device__ __nv_bfloat16 g_histb[ROWS_ * NK_ + 64];   // decoder h1 history bf16 (+pad)
__device__ float         g_biasI0[2][G4_];            // layer0 bias (folded into pre)
__device__ float         g_biasI1[2][G4_];            // layer1 bias
__device__ float         g_sumexp[ROWS_];
__device__ float         g_tgt[ROWS_];
__device__ unsigned      g_cnt;                       // grid barrier arrivals (monotonic)

// ---------------- helpers ----------------
__device__ __forceinline__ unsigned smem_u32(const void* p) {
    return (unsigned)__cvta_generic_to_shared(p);
}
__device__ __forceinline__ void ldsm4(unsigned a[4], unsigned addr) {
    asm volatile("ldmatrix.sync.aligned.m8n8.x4.shared.b16 {%0,%1,%2,%3}, [%4];"
        : "=r"(a[0]), "=r"(a[1]), "=r"(a[2]), "=r"(a[3]) : "r"(addr));
}
__device__ __forceinline__ void mma_bf16(float c[4], const unsigned a[4], unsigned b0, unsigned b1) {
    asm volatile("mma.sync.aligned.m16n8k16.row.col.f32.bf16.bf16.f32 "
        "{%0,%1,%2,%3},{%4,%5,%6,%7},{%8,%9},{%0,%1,%2,%3};"
        : "+f"(c[0]), "+f"(c[1]), "+f"(c[2]), "+f"(c[3])
        : "r"(a[0]), "r"(a[1]), "r"(a[2]), "r"(a[3]), "r"(b0), "r"(b1));
}
__device__ __forceinline__ float sigf(float x) {
    return __fdividef(1.f, 1.f + __expf(-x));
}
__device__ __forceinline__ float tanh_f(float x) {
    float t = __expf(2.f * x);
    return __fdividef(t - 1.f, t + 1.f);
}
__device__ __forceinline__ unsigned short bfc(float v) {
    return __bfloat16_as_ushort(__float2bfloat16(v));
}
__device__ __forceinline__ void bulk_cp(unsigned dst, const void* src, unsigned bytes,
                                        unsigned mbar) {
    asm volatile(
        "cp.async.bulk.shared::cluster.global.mbarrier::complete_tx::bytes [%0], [%1], %2, [%3];"
        :: "r"(dst), "l"(src), "r"(bytes), "r"(mbar) : "memory");
}
__device__ __forceinline__ void mbar_expect_tx(unsigned mbar, unsigned bytes) {
    asm volatile("mbarrier.arrive.expect_tx.shared.b64 _, [%0], %1;"
        :: "r"(mbar), "r"(bytes) : "memory");
}
__device__ __forceinline__ void mbar_wait(unsigned mbar, unsigned parity) {
    unsigned done;
    asm volatile(
        "{\n\t.reg .pred p;\n\t"
        "mbarrier.try_wait.parity.acquire.cta.shared::cta.b64 p, [%1], %2;\n\t"
        "selp.b32 %0, 1, 0, p;\n\t}"
        : "=r"(done) : "r"(mbar), "r"(parity) : "memory");
    while (!done) {
        asm volatile(
            "{\n\t.reg .pred p;\n\t"
            "mbarrier.try_wait.parity.acquire.cta.shared::cta.b64 p, [%1], %2, 0x989680;\n\t"
            "selp.b32 %0, 1, 0, p;\n\t}"
            : "=r"(done) : "r"(mbar), "r"(parity) : "memory");
    }
}

// ---------------- combo: weight conversion (y<6) + setup (y==6) ----------------
struct ConvArgs {
    const float* w[6];
    const float* b[8];   // eb0a, eb0b, db0a, db0b, eb1a, eb1b, db1a, db1b
};

__global__ __launch_bounds__(256) void conv_setup(ConvArgs a) {
    if (blockIdx.y < 6) {
        const int slot = blockIdx.y;
        const float* __restrict__ src = a.w[slot];
        int idx = blockIdx.x * blockDim.x + threadIdx.x;
        if (idx >= NPAD_ * (SROW_ / 2)) return;
        int n = idx / (SROW_ / 2), q = idx - n * (SROW_ / 2), k = q * 2;
        float2 v = make_float2(0.f, 0.f);
        if (n < G4_ && k < HID_) {
            int j = n >> 2, g = n & 3;
            v = *(const float2*)&src[(size_t)(g * HID_ + j) * HID_ + k];
        }
        unsigned o = ((unsigned)bfc(v.y) << 16) | (unsigned)bfc(v.x);
        *(unsigned*)&g_Wb[slot][n * SROW_ + k] = o;
        return;
    }
    // ---- setup branch (y == 6) ----
    const int stride = gridDim.x * blockDim.x;
    const int i0 = blockIdx.x * blockDim.x + threadIdx.x;
    const __nv_bfloat16 z = __float2bfloat16(0.f);
    for (int i = i0; i < B_ * SROW_; i += stride) {
        g_hb[0][0][i] = z; g_hb[0][1][i] = z;
        g_hb[1][0][i] = z; g_hb[1][1][i] = z;
    }
    for (int i = i0; i < ROWS_; i += stride) { g_sumexp[i] = 0.f; g_tgt[i] = 0.f; }
    for (int i = i0; i < ROWS_ * 12; i += stride) {
        int r = i / 12, k = HID_ + i - r * 12;
        g_histb[r * NK_ + k] = z;
    }
    for (int t = i0; t < 2 * G4_; t += stride) {
        int sel = t / G4_, n = t - sel * G4_;
        int j = n >> 2, g = n & 3;
        g_biasI0[sel][n] = (sel ? a.b[2] : a.b[0])[g * HID_ + j]
                         + (sel ? a.b[3] : a.b[1])[g * HID_ + j];
        g_biasI1[sel][n] = (sel ? a.b[6] : a.b[4])[g * HID_ + j]
                         + (sel ? a.b[7] : a.b[5])[g * HID_ + j];
    }
    if (blockIdx.x == 0 && threadIdx.x == 0) g_cnt = 0u;
}

// ---------------- fused input projection: gather + convert + GEMM + bias ----------------
__global__ __launch_bounds__(256) void pre_gemm(
    const int* __restrict__ x, const int* __restrict__ y,
    const float* __restrict__ encemb, const float* __restrict__ decemb,
    const float* __restrict__ Wih0e, const float* __restrict__ Wih0d)
{
    extern __shared__ __align__(16) unsigned short psm[];
    unsigned short* sA = psm;
    unsigned short* sB = psm + 128 * XROW_;
    const int tid = threadIdx.x, lane = tid & 31, warp = tid >> 5;
    const int which = blockIdx.y >> 4, mtile = blockIdx.y & 15;
    const int m0 = mtile * 128, n0 = blockIdx.x * 64;
    const int* idx = which ? y : x;
    const float* emb = which ? decemb : encemb;
    const float* Wsrc = which ? Wih0d : Wih0e;

    {
        const int r = tid >> 1, h = tid & 1;
        const int tok = idx[m0 + r];
        const float4* es = (const float4*)(emb + (size_t)tok * EMB_ + h * 128);
        unsigned short* drow = sA + r * XROW_ + h * 128;
        #pragma unroll
        for (int q = 0; q < 32; q++) {
            float4 v = es[q];
            ushort4 o;
            o.x = bfc(v.x); o.y = bfc(v.y); o.z = bfc(v.z); o.w = bfc(v.w);
            *(ushort4*)(drow + q * 4) = o;
        }
    }
    {
        const int rb = tid >> 2, qt = tid & 3;
        const int n = n0 + rb;
        unsigned short* drow = sB + rb * XROW_ + qt * 64;
        if (n < G4_) {
            const int j = n >> 2, g = n & 3;
            const float4* ws = (const float4*)(Wsrc + (size_t)(g * HID_ + j) * EMB_ + qt * 64);
            #pragma unroll
            for (int q = 0; q < 16; q++) {
                float4 v = ws[q];
                ushort4 o;
                o.x = bfc(v.x); o.y = bfc(v.y); o.z = bfc(v.z); o.w = bfc(v.w);
                *(ushort4*)(drow + q * 4) = o;
            }
        } else {
            ushort4 zz = make_ushort4(0, 0, 0, 0);
            #pragma unroll
            for (int q = 0; q < 16; q++) *(ushort4*)(drow + q * 4) = zz;
        }
    }
    __syncthreads();

    const int wm = warp >> 2, wn = warp & 3;
    float acc[4][2][4];
    #pragma unroll
    for (int a = 0; a < 4; a++) for (int b = 0; b < 2; b++) for (int r = 0; r < 4; r++)
        acc[a][b][r] = 0.f;

    const unsigned sbA = smem_u32(sA);
    const unsigned a_off =
        (((unsigned)((lane & 7) + ((lane >> 3) & 1) * 8)) * XROW_ + (unsigned)(lane >> 4) * 8) * 2;
    const unsigned short* brow = sB + (wn * 16 + (lane >> 2)) * XROW_ + (lane & 3) * 2;

    #pragma unroll 4
    for (int ki = 0; ki < 16; ki++) {
        const int k0 = ki * 16;
        unsigned av[4][4];
        #pragma unroll
        for (int mt = 0; mt < 4; mt++)
            ldsm4(av[mt], sbA + a_off + (unsigned)((wm * 64 + mt * 16) * XROW_ + k0) * 2);
        #pragma unroll
        for (int nt = 0; nt < 2; nt++) {
            unsigned b0 = *(const unsigned*)(brow + nt * 8 * XROW_ + k0);
            unsigned b1 = *(const unsigned*)(brow + nt * 8 * XROW_ + k0 + 8);
            #pragma unroll
            for (int mt = 0; mt < 4; mt++) mma_bf16(acc[mt][nt], av[mt], b0, b1);
        }
    }

    float ex[4][2][4];
    #pragma unroll
    for (int a = 0; a < 4; a++) for (int b = 0; b < 2; b++) for (int r = 0; r < 4; r++)
        ex[a][b][r] = __shfl_xor_sync(0xffffffffu, acc[a][b][r], 1);

    if (!(lane & 1)) {
        #pragma unroll
        for (int mt = 0; mt < 4; mt++) {
            #pragma unroll
            for (int nt = 0; nt < 2; nt++) {
                const int cn = n0 + wn * 16 + nt * 8 + (lane & 3) * 2;
                if (cn >= G4_) continue;
                const float4 bi = *(const float4*)&g_biasI0[which][cn];
                #pragma unroll
                for (int half = 0; half < 2; half++) {
                    const int row = m0 + wm * 64 + mt * 16 + half * 8 + (lane >> 2);
                    float4 o4;
                    o4.x = acc[mt][nt][half * 2 + 0] + bi.x;
                    o4.y = acc[mt][nt][half * 2 + 1] + bi.y;
                    o4.z = ex[mt][nt][half * 2 + 0] + bi.z;
                    o4.w = ex[mt][nt][half * 2 + 1] + bi.w;
                    *(float4*)&g_pre[which][(size_t)row * G4_ + cn] = o4;
                }
            }
        }
    }
}

// ---------------- persistent scan (unchanged from R12 best) ----------------
__device__ __forceinline__ void gbar(int s) {
    __syncthreads();
    if (threadIdx.x == 0) {
        asm volatile("red.release.gpu.global.add.u32 [%0], %1;"
            :: "l"(&g_cnt), "r"(1u) : "memory");
        const unsigned target = (unsigned)SCANB_ * (unsigned)(s + 1);
        unsigned v;
        do {
            asm volatile("ld.acquire.gpu.global.u32 %0, [%1];"
                : "=r"(v) : "l"(&g_cnt) : "memory");
        } while (v < target);
    }
    __syncthreads();
}

__device__ __forceinline__ void gemm_w(const unsigned short* wrow, unsigned abase,
                                       float acc[4]) {
    #pragma unroll 4
    for (int ki = 0; ki < NKI_; ki++) {
        const int k0 = ki * 16;
        unsigned av[4];
        ldsm4(av, abase + (unsigned)k0 * 2);
        unsigned b0 = *(const unsigned*)(wrow + k0);
        unsigned b1 = *(const unsigned*)(wrow + k0 + 8);
        mma_bf16(acc, av, b0, b1);
    }
}

__global__ __launch_bounds__(256) void scan_kernel() {
    extern __shared__ __align__(16) unsigned short ssm[];
    unsigned short* sWa = ssm + 2 * 32 * SROW_;
    unsigned short* sWb = ssm + 3 * 32 * SROW_;
    const unsigned sbase = smem_u32(ssm);
    const unsigned mbarA = sbase + 4u * BUFB_;
    const unsigned mbarB = sbase + 4u * BUFB_ + 16u;
    const int bid = blockIdx.x;
    const int layer = (bid >= 66) ? 1 : 0;
    const int tile = layer ? bid - 66 : bid;
    const int tid = threadIdx.x, lane = tid & 31, warp = tid >> 5;
    const int mt = warp >> 2, nt = warp & 3;
    const int m_off = mt * 16;
    const int nw = tile * 32 + nt * 8;
    const int cn = nw + (lane & 3) * 2;
    const int j = cn >> 2;
    const bool epi = (!(lane & 1)) && (cn < G4_);
    const int b0r = m_off + (lane >> 2);
    const int b1r = b0r + 8;
    const size_t woff = (size_t)tile * 32 * SROW_;

    if (tid == 0) {
        asm volatile("mbarrier.init.shared.b64 [%0], %1;" :: "r"(mbarA), "r"(1u) : "memory");
        asm volatile("mbarrier.init.shared.b64 [%0], %1;" :: "r"(mbarB), "r"(1u) : "memory");
    }
    __syncthreads();

    const unsigned a_off =
        (((unsigned)((lane & 7) + ((lane >> 3) & 1) * 8)) * SROW_ + (unsigned)(lane >> 4) * 8) * 2;
    const unsigned a0base = sbase + (unsigned)m_off * SROW_ * 2 + a_off;
    const unsigned a1base = sbase + BUFB_ + (unsigned)m_off * SROW_ * 2 + a_off;
    const unsigned short* wrowA = sWa + (nt * 8 + (lane >> 2)) * SROW_ + (lane & 3) * 2;
    const unsigned short* wrowB = sWb + (nt * 8 + (lane >> 2)) * SROW_ + (lane & 3) * 2;

    float creg0 = 0.f, creg1 = 0.f;

    for (int s = 0; s <= 128; s++) {
        if (tid == 0) {
            if (layer == 0) {
                unsigned tx = BUFB_ + ((s == 0 || s == 64) ? BUFB_ : 0u);
                mbar_expect_tx(mbarA, tx);
                bulk_cp(sbase, g_hb[0][(s & 1) ^ 1], BUFB_, mbarA);
                if (s == 0)  bulk_cp(sbase + 2u * BUFB_, g_Wb[0] + woff, BUFB_, mbarA);
                if (s == 64) bulk_cp(sbase + 2u * BUFB_, g_Wb[3] + woff, BUFB_, mbarA);
            } else {
                const bool wslot = (s == 0 || s == 65);
                unsigned txA = BUFB_ + (wslot ? BUFB_ : 0u);
                unsigned txB = BUFB_ + (wslot ? BUFB_ : 0u);
                mbar_expect_tx(mbarA, txA);
                mbar_expect_tx(mbarB, txB);
                bulk_cp(sbase, g_hb[0][(s & 1) ^ 1], BUFB_, mbarA);
                bulk_cp(sbase + BUFB_, g_hb[1][s & 1], BUFB_, mbarB);
                if (s == 0) {
                    bulk_cp(sbase + 2u * BUFB_, g_Wb[1] + woff, BUFB_, mbarA);
                    bulk_cp(sbase + 3u * BUFB_, g_Wb[2] + woff, BUFB_, mbarB);
                }
                if (s == 65) {
                    bulk_cp(sbase + 2u * BUFB_, g_Wb[4] + woff, BUFB_, mbarA);
                    bulk_cp(sbase + 3u * BUFB_, g_Wb[5] + woff, BUFB_, mbarB);
                }
            }
        }

        const bool active = layer ? (s >= 1) : (s <= 127);
        const int z = s - 1;
        const int sel = layer ? (z >= 64 ? 1 : 0) : (s >= 64 ? 1 : 0);
        const int tstep = layer ? (sel ? z - 64 : z) : (sel ? s - 64 : s);

        float4 add0, add1;
        if (active && epi) {
            if (layer) {
                add0 = *(const float4*)&g_biasI1[sel][cn];
                add1 = add0;
            } else {
                add0 = *(const float4*)&g_pre[sel][(size_t)(tstep * B_ + b0r) * G4_ + cn];
                add1 = *(const float4*)&g_pre[sel][(size_t)(tstep * B_ + b1r) * G4_ + cn];
            }
        }

        mbar_wait(mbarA, s & 1);

        if (active) {
            float acc[4] = {0.f, 0.f, 0.f, 0.f};
            if (layer) {
                gemm_w(wrowA, a0base, acc);
                mbar_wait(mbarB, s & 1);
                gemm_w(wrowB, a1base, acc);
            } else {
                gemm_w(wrowA, a0base, acc);
            }
            float ex[4];
            #pragma unroll
            for (int r = 0; r < 4; r++)
                ex[r] = __shfl_xor_sync(0xffffffffu, acc[r], 1);

            if (epi) {
                __nv_bfloat16* hout = layer ? g_hb[1][(s & 1) ^ 1] : g_hb[0][s & 1];
                {
                    float iv = sigf(acc[0] + add0.x);
                    float fv = sigf(acc[1] + add0.y);
                    float gv = tanh_f(ex[0] + add0.z);
                    float ov = sigf(ex[1] + add0.w);
                    creg0 = fv * creg0 + iv * gv;
                    float h = ov * tanh_f(creg0);
                    __nv_bfloat16 hb = __float2bfloat16(h);
                    hout[b0r * SROW_ + j] = hb;
                    if (layer && sel) g_histb[(size_t)(tstep * B_ + b0r) * NK_ + j] = hb;
                }
                {
                    float iv = sigf(acc[2] + add1.x);
                    float fv = sigf(acc[3] + add1.y);
                    float gv = tanh_f(ex[2] + add1.z);
                    float ov = sigf(ex[3] + add1.w);
                    creg1 = fv * creg1 + iv * gv;
                    float h = ov * tanh_f(creg1);
                    __nv_bfloat16 hb = __float2bfloat16(h);
                    hout[b1r * SROW_ + j] = hb;
                    if (layer && sel) g_histb[(size_t)(tstep * B_ + b1r) * NK_ + j] = hb;
                }
            }
        } else if (layer) {
            mbar_wait(mbarB, s & 1);
        }
        if (s < 128) gbar(s);
    }
}

// ---------------- fused vocab projection + CE: N-tile 64, 2 blocks/SM ----------------
// grid 500 blocks x 256 thr. Block owns 64-vocab N-tile (resident bf16 in smem),
// loops all 16 M-tiles with double-buffered 64-wide cp.async A chunks.
// Warps: wm 0..1 (M=64 each), wn 0..3 (N=16 each: 2 n8 tiles).
#define SROWCE_ 536
__global__ __launch_bounds__(256, 2) void ce2(const float* __restrict__ Wout,
                                              const float* __restrict__ bout,
                                              const int* __restrict__ y) {
    extern __shared__ __align__(16) unsigned short csm[];
    unsigned short* sB = csm;                       // [64][SROWCE_] bf16 Wout tile
    unsigned short* sA = csm + 64 * SROWCE_;        // 2 x [128][CROW2_]
    const int tid = threadIdx.x, lane = tid & 31, warp = tid >> 5;
    const int bx = blockIdx.x;

    // ---- load + convert B tile fp32 -> bf16 (once): 64 rows, 4 threads/row ----
    {
        const int r = tid >> 2, qt = tid & 3;
        const int n = bx * 64 + r;
        const float4* src = (const float4*)(Wout + (size_t)n * HID_);
        unsigned short* drow = sB + r * SROWCE_;
        for (int q = qt; q < 129; q += 4) {
            float4 v = src[q];
            ushort4 o;
            o.x = bfc(v.x); o.y = bfc(v.y); o.z = bfc(v.z); o.w = bfc(v.w);
            *(ushort4*)(drow + q * 4) = o;
        }
        if (qt == 0) {   // zero pad cols 516..527
            ushort4 zz = make_ushort4(0, 0, 0, 0);
            *(ushort4*)(drow + 516) = zz;
            *(ushort4*)(drow + 520) = zz;
            *(ushort4*)(drow + 524) = zz;
        }
    }

    const int wm = warp >> 2, wn = warp & 3;
    const unsigned sbA = smem_u32(sA);
    const unsigned sbB = smem_u32(sB);
    const unsigned bufB = (unsigned)128 * CROW2_ * 2;
    const unsigned a_off =
        (((unsigned)((lane & 7) + ((lane >> 3) & 1) * 8)) * CROW2_ + (unsigned)(lane >> 4) * 8) * 2;
    // B ldsm.x4: matrices (nt0,k0),(nt0,k8),(nt1,k0),(nt1,k8)
    const unsigned b_row = (unsigned)(wn * 16 + ((lane >> 4) & 1) * 8 + (lane & 7));
    const unsigned b_kh  = (unsigned)(((lane >> 3) & 1) * 8);
    const unsigned bB0 = sbB + (b_row * SROWCE_ + b_kh) * 2;

    const int sr = tid >> 1, sh = tid & 1;

    #define CSTAGE(MT, C) do { \
        const size_t srcbase = (size_t)((MT) * 128 + sr) * NK_ + (C) * 64; \
        unsigned dstr = smem_u32(sA) + ((unsigned)((C) & 1)) * bufB \
                      + (unsigned)(sr * CROW2_) * 2; \
        if ((C) < 8) { \
            const char* s0 = (const char*)(g_histb + srcbase + sh * 32); \
            unsigned d0 = dstr + (unsigned)(sh * 32) * 2; \
            asm volatile("cp.async.cg.shared.global [%0], [%1], 16;" :: "r"(d0), "l"(s0)); \
            asm volatile("cp.async.cg.shared.global [%0], [%1], 16;" :: "r"(d0 + 16), "l"(s0 + 16)); \
            asm volatile("cp.async.cg.shared.global [%0], [%1], 16;" :: "r"(d0 + 32), "l"(s0 + 32)); \
            asm volatile("cp.async.cg.shared.global [%0], [%1], 16;" :: "r"(d0 + 48), "l"(s0 + 48)); \
        } else { \
            const char* s0 = (const char*)(g_histb + srcbase + sh * 8); \
            unsigned d0 = dstr + (unsigned)(sh * 8) * 2; \
            asm volatile("cp.async.cg.shared.global [%0], [%1], 16;" :: "r"(d0), "l"(s0)); \
        } \
        asm volatile("cp.async.commit_group;"); \
    } while (0)

    __syncthreads();   // sB ready

    for (int mt = 0; mt < 16; mt++) {
        float acc[4][2][4];
        #pragma unroll
        for (int a = 0; a < 4; a++) for (int b = 0; b < 2; b++) for (int r = 0; r < 4; r++)
            acc[a][b][r] = 0.f;

        CSTAGE(mt, 0);
        for (int c = 0; c < 9; c++) {
            if (c + 1 < 9) {
                CSTAGE(mt, c + 1);
                asm volatile("cp.async.wait_group 1;");
            } else {
                asm volatile("cp.async.wait_group 0;");
            }
            __syncthreads();
            const unsigned chbase = sbA + ((unsigned)(c & 1)) * bufB + a_off;
            const int nk16 = (c == 8) ? 1 : 4;
            for (int kk = 0; kk < nk16; kk++) {
                unsigned av[4][4];
                #pragma unroll
                for (int q = 0; q < 4; q++)
                    ldsm4(av[q], chbase + (unsigned)((wm * 64 + q * 16) * CROW2_ + kk * 16) * 2);
                const int k0 = c * 64 + kk * 16;
                unsigned bv[4];
                ldsm4(bv, bB0 + (unsigned)k0 * 2);
                #pragma unroll
                for (int q = 0; q < 4; q++) {
                    mma_bf16(acc[q][0], av[q], bv[0], bv[1]);
                    mma_bf16(acc[q][1], av[q], bv[2], bv[3]);
                }
            }
            __syncthreads();
        }

        // epilogue for this m-tile
        #pragma unroll
        for (int q = 0; q < 4; q++) {
            const int r0 = mt * 128 + wm * 64 + q * 16 + (lane >> 2);
            const int r1 = r0 + 8;
            const int tg0 = y[r0 + 32];
            const int tg1 = y[r1 + 32];
            float s0 = 0.f, s1 = 0.f;
            #pragma unroll
            for (int nt = 0; nt < 2; nt++) {
                const int cnv = bx * 64 + wn * 16 + nt * 8 + (lane & 3) * 2;
                const float2 bo = *(const float2*)&bout[cnv];
                float l0 = acc[q][nt][0] + bo.x;
                float l1 = acc[q][nt][1] + bo.y;
                float l2 = acc[q][nt][2] + bo.x;
                float l3 = acc[q][nt][3] + bo.y;
                s0 += __expf(l0) + __expf(l1);
                s1 += __expf(l2) + __expf(l3);
                if (cnv == tg0)     atomicAdd(&g_tgt[r0], l0);
                if (cnv + 1 == tg0) atomicAdd(&g_tgt[r0], l1);
                if (cnv == tg1)     atomicAdd(&g_tgt[r1], l2);
                if (cnv + 1 == tg1) atomicAdd(&g_tgt[r1], l3);
            }
            s0 += __shfl_xor_sync(0xffffffffu, s0, 1);
            s0 += __shfl_xor_sync(0xffffffffu, s0, 2);
            s1 += __shfl_xor_sync(0xffffffffu, s1, 1);
            s1 += __shfl_xor_sync(0xffffffffu, s1, 2);
            if (!(lane & 3)) {
                atomicAdd(&g_sumexp[r0], s0);
                atomicAdd(&g_sumexp[r1], s1);
            }
        }
    }
    #undef CSTAGE
}

// ---------------- final reduction ----------------
__global__ __launch_bounds__(256) void finalize_kernel(float* out) {
    __shared__ float sm[256];
    float s = 0.f;
    for (int r = threadIdx.x; r < ROWS_; r += 256)
        s += logf(g_sumexp[r]) - g_tgt[r];
    sm[threadIdx.x] = s;
    __syncthreads();
    for (int st = 128; st; st >>= 1) {
        if (threadIdx.x < st) sm[threadIdx.x] += sm[threadIdx.x + st];
        __syncthreads();
    }
    if (threadIdx.x == 0) out[0] = sm[0] / 32.f;
}

// ---------------- host launcher ----------------
extern "C" void kernel_launch(void* const* d_in, const int* in_sizes, int n_in,
                              void* d_out, int out_size)
{
    (void)in_sizes; (void)n_in; (void)out_size;
    const int*   x        = (const int*)  d_in[0];
    const int*   y        = (const int*)  d_in[1];
    const float* encemb   = (const float*)d_in[2];
    const float* decemb   = (const float*)d_in[3];
    const float* enc_Wih0 = (const float*)d_in[4];
    const float* enc_Whh0 = (const float*)d_in[5];
    const float* enc_bih0 = (const float*)d_in[6];
    const float* enc_bhh0 = (const float*)d_in[7];
    const float* enc_Wih1 = (const float*)d_in[8];
    const float* enc_Whh1 = (const float*)d_in[9];
    const float* enc_bih1 = (const float*)d_in[10];
    const float* enc_bhh1 = (const float*)d_in[11];
    const float* dec_Wih0 = (const float*)d_in[12];
    const float* dec_Whh0 = (const float*)d_in[13];
    const float* dec_bih0 = (const float*)d_in[14];
    const float* dec_bhh0 = (const float*)d_in[15];
    const float* dec_Wih1 = (const float*)d_in[16];
    const float* dec_Whh1 = (const float*)d_in[17];
    const float* dec_bih1 = (const float*)d_in[18];
    const float* dec_bhh1 = (const float*)d_in[19];
    const float* Wout     = (const float*)d_in[20];
    const float* bout     = (const float*)d_in[21];
    float* out = (float*)d_out;

    const int PRE_SMEM  = (128 + 64) * XROW_ * 2;                     // 101,376
    const int SCAN_SMEM = 4 * BUFB_ + 32;                             // 137,248
    const int CE_SMEM   = 64 * SROWCE_ * 2 + 2 * 128 * CROW2_ * 2;    // 105,472
    cudaFuncSetAttribute(pre_gemm,    cudaFuncAttributeMaxDynamicSharedMemorySize, PRE_SMEM);
    cudaFuncSetAttribute(scan_kernel, cudaFuncAttributeMaxDynamicSharedMemorySize, SCAN_SMEM);
    cudaFuncSetAttribute(ce2,         cudaFuncAttributeMaxDynamicSharedMemorySize, CE_SMEM);

    // launch order: harness emits 2 launches first; ce2 (our #3) lands at
    // global #5 where ncu -s 5 -c 1 samples.
    ConvArgs ca;
    ca.w[0] = enc_Whh0; ca.w[1] = enc_Wih1; ca.w[2] = enc_Whh1;
    ca.w[3] = dec_Whh0; ca.w[4] = dec_Wih1; ca.w[5] = dec_Whh1;
    ca.b[0] = enc_bih0; ca.b[1] = enc_bhh0; ca.b[2] = dec_bih0; ca.b[3] = dec_bhh0;
    ca.b[4] = enc_bih1; ca.b[5] = enc_bhh1; ca.b[6] = dec_bih1; ca.b[7] = dec_bhh1;
    const int GC = (NPAD_ * (SROW_ / 2) + 255) / 256;
    conv_setup<<<dim3(GC, 7), 256>>>(ca);                                    // 0

    pre_gemm<<<dim3(33, 32), 256, PRE_SMEM>>>(x, y, encemb, decemb,          // 1
                                              enc_Wih0, dec_Wih0);

    scan_kernel<<<SCANB_, 256, SCAN_SMEM>>>();                               // 2

    ce2<<<500, 256, CE_SMEM>>>(Wout, bout, y);                               // 3  <- ncu sample

    finalize_kernel<<<1, 256>>>(out);                                        // 4
}

// round 16
// speedup vs baseline: 1.0791x; 1.0791x over previous
#include <cuda_runtime.h>
#include <cuda_bf16.h>
#include <math.h>

#define B_    32
#define EMB_  256
#define HID_  516
#define G4_   2064     // 4*HID_
#define V_    32000
#define ROWS_ 2048     // 64*32 decoder rows
#define NK_   528      // K padded to multiple of 16 (hist layout)
#define NKI_  33       // k-iterations of 16
#define SROW_ 536      // row stride (u16) for h/W tiles, ldmatrix conflict-free
#define XROW_ 264      // smem row stride (u16) for K=256 tiles
#define NPAD_ 2112     // gate-col dim padded (66 tiles * 32)
#define SCANB_ 132     // scan blocks (<=148, all co-resident)
#define CROW2_ 72      // CE A-chunk row stride (u16), 64 cols + pad
#define BUFB_  34304   // one staged buffer: 32*SROW_*2 bytes

// ---------------- scratch (static device globals; no allocation) ----------------
__device__ __nv_bfloat16 g_Wb[6][NPAD_ * SROW_];      // scan weights bf16, PADDED rows
__device__ float         g_pre[2][ROWS_ * G4_];       // input proj + bias, gate-interleaved
__device__ __nv_bfloat16 g_hb[2][2][B_ * SROW_];      // h state [layer][buf], PADDED rows
__device__ __nv_bfloat16 g_histb[ROWS_ * NK_ + 64];   // decoder h1 history bf16 (+pad)
__device__ float         g_biasI0[2][G4_];            // layer0 bias (folded into pre)
__device__ float         g_biasI1[2][G4_];            // layer1 bias
__device__ float         g_sumexp[ROWS_];
__device__ float         g_tgt[ROWS_];
__device__ unsigned      g_cnt;                       // grid barrier arrivals (monotonic)

// ---------------- helpers ----------------
__device__ __forceinline__ unsigned smem_u32(const void* p) {
    return (unsigned)__cvta_generic_to_shared(p);
}
__device__ __forceinline__ void ldsm4(unsigned a[4], unsigned addr) {
    asm volatile("ldmatrix.sync.aligned.m8n8.x4.shared.b16 {%0,%1,%2,%3}, [%4];"
        : "=r"(a[0]), "=r"(a[1]), "=r"(a[2]), "=r"(a[3]) : "r"(addr));
}
__device__ __forceinline__ void mma_bf16(float c[4], const unsigned a[4], unsigned b0, unsigned b1) {
    asm volatile("mma.sync.aligned.m16n8k16.row.col.f32.bf16.bf16.f32 "
        "{%0,%1,%2,%3},{%4,%5,%6,%7},{%8,%9},{%0,%1,%2,%3};"
        : "+f"(c[0]), "+f"(c[1]), "+f"(c[2]), "+f"(c[3])
        : "r"(a[0]), "r"(a[1]), "r"(a[2]), "r"(a[3]), "r"(b0), "r"(b1));
}
__device__ __forceinline__ float sigf(float x) {
    return __fdividef(1.f, 1.f + __expf(-x));
}
__device__ __forceinline__ float tanh_f(float x) {
    float t = __expf(2.f * x);
    return __fdividef(t - 1.f, t + 1.f);
}
__device__ __forceinline__ unsigned short bfc(float v) {
    return __bfloat16_as_ushort(__float2bfloat16(v));
}
__device__ __forceinline__ void bulk_cp(unsigned dst, const void* src, unsigned bytes,
                                        unsigned mbar) {
    asm volatile(
        "cp.async.bulk.shared::cluster.global.mbarrier::complete_tx::bytes [%0], [%1], %2, [%3];"
        :: "r"(dst), "l"(src), "r"(bytes), "r"(mbar) : "memory");
}
__device__ __forceinline__ void mbar_expect_tx(unsigned mbar, unsigned bytes) {
    asm volatile("mbarrier.arrive.expect_tx.shared.b64 _, [%0], %1;"
        :: "r"(mbar), "r"(bytes) : "memory");
}
__device__ __forceinline__ void mbar_wait(unsigned mbar, unsigned parity) {
    unsigned done;
    asm volatile(
        "{\n\t.reg .pred p;\n\t"
        "mbarrier.try_wait.parity.acquire.cta.shared::cta.b64 p, [%1], %2;\n\t"
        "selp.b32 %0, 1, 0, p;\n\t}"
        : "=r"(done) : "r"(mbar), "r"(parity) : "memory");
    while (!done) {
        asm volatile(
            "{\n\t.reg .pred p;\n\t"
            "mbarrier.try_wait.parity.acquire.cta.shared::cta.b64 p, [%1], %2, 0x989680;\n\t"
            "selp.b32 %0, 1, 0, p;\n\t}"
            : "=r"(done) : "r"(mbar), "r"(parity) : "memory");
    }
}

// ---------------- combo: weight conversion (y<6) + setup (y==6) ----------------
struct ConvArgs {
    const float* w[6];
    const float* b[8];   // eb0a, eb0b, db0a, db0b, eb1a, eb1b, db1a, db1b
};

__global__ __launch_bounds__(256) void conv_setup(ConvArgs a) {
    if (blockIdx.y < 6) {
        const int slot = blockIdx.y;
        const float* __restrict__ src = a.w[slot];
        int idx = blockIdx.x * blockDim.x + threadIdx.x;
        if (idx >= NPAD_ * (SROW_ / 2)) return;
        int n = idx / (SROW_ / 2), q = idx - n * (SROW_ / 2), k = q * 2;
        float2 v = make_float2(0.f, 0.f);
        if (n < G4_ && k < HID_) {
            int j = n >> 2, g = n & 3;
            v = *(const float2*)&src[(size_t)(g * HID_ + j) * HID_ + k];
        }
        unsigned o = ((unsigned)bfc(v.y) << 16) | (unsigned)bfc(v.x);
        *(unsigned*)&g_Wb[slot][n * SROW_ + k] = o;
        return;
    }
    // ---- setup branch (y == 6) ----
    const int stride = gridDim.x * blockDim.x;
    const int i0 = blockIdx.x * blockDim.x + threadIdx.x;
    const __nv_bfloat16 z = __float2bfloat16(0.f);
    for (int i = i0; i < B_ * SROW_; i += stride) {
        g_hb[0][0][i] = z; g_hb[0][1][i] = z;
        g_hb[1][0][i] = z; g_hb[1][1][i] = z;
    }
    for (int i = i0; i < ROWS_; i += stride) { g_sumexp[i] = 0.f; g_tgt[i] = 0.f; }
    for (int i = i0; i < ROWS_ * 12; i += stride) {
        int r = i / 12, k = HID_ + i - r * 12;
        g_histb[r * NK_ + k] = z;
    }
    for (int t = i0; t < 2 * G4_; t += stride) {
        int sel = t / G4_, n = t - sel * G4_;
        int j = n >> 2, g = n & 3;
        g_biasI0[sel][n] = (sel ? a.b[2] : a.b[0])[g * HID_ + j]
                         + (sel ? a.b[3] : a.b[1])[g * HID_ + j];
        g_biasI1[sel][n] = (sel ? a.b[6] : a.b[4])[g * HID_ + j]
                         + (sel ? a.b[7] : a.b[5])[g * HID_ + j];
    }
    if (blockIdx.x == 0 && threadIdx.x == 0) g_cnt = 0u;
}

// ---------------- fused input projection: gather + convert + GEMM + bias ----------------
__global__ __launch_bounds__(256) void pre_gemm(
    const int* __restrict__ x, const int* __restrict__ y,
    const float* __restrict__ encemb, const float* __restrict__ decemb,
    const float* __restrict__ Wih0e, const float* __restrict__ Wih0d)
{
    extern __shared__ __align__(16) unsigned short psm[];
    unsigned short* sA = psm;
    unsigned short* sB = psm + 128 * XROW_;
    const int tid = threadIdx.x, lane = tid & 31, warp = tid >> 5;
    const int which = blockIdx.y >> 4, mtile = blockIdx.y & 15;
    const int m0 = mtile * 128, n0 = blockIdx.x * 64;
    const int* idx = which ? y : x;
    const float* emb = which ? decemb : encemb;
    const float* Wsrc = which ? Wih0d : Wih0e;

    {
        const int r = tid >> 1, h = tid & 1;
        const int tok = idx[m0 + r];
        const float4* es = (const float4*)(emb + (size_t)tok * EMB_ + h * 128);
        unsigned short* drow = sA + r * XROW_ + h * 128;
        #pragma unroll
        for (int q = 0; q < 32; q++) {
            float4 v = es[q];
            ushort4 o;
            o.x = bfc(v.x); o.y = bfc(v.y); o.z = bfc(v.z); o.w = bfc(v.w);
            *(ushort4*)(drow + q * 4) = o;
        }
    }
    {
        const int rb = tid >> 2, qt = tid & 3;
        const int n = n0 + rb;
        unsigned short* drow = sB + rb * XROW_ + qt * 64;
        if (n < G4_) {
            const int j = n >> 2, g = n & 3;
            const float4* ws = (const float4*)(Wsrc + (size_t)(g * HID_ + j) * EMB_ + qt * 64);
            #pragma unroll
            for (int q = 0; q < 16; q++) {
                float4 v = ws[q];
                ushort4 o;
                o.x = bfc(v.x); o.y = bfc(v.y); o.z = bfc(v.z); o.w = bfc(v.w);
                *(ushort4*)(drow + q * 4) = o;
            }
        } else {
            ushort4 zz = make_ushort4(0, 0, 0, 0);
            #pragma unroll
            for (int q = 0; q < 16; q++) *(ushort4*)(drow + q * 4) = zz;
        }
    }
    __syncthreads();

    const int wm = warp >> 2, wn = warp & 3;
    float acc[4][2][4];
    #pragma unroll
    for (int a = 0; a < 4; a++) for (int b = 0; b < 2; b++) for (int r = 0; r < 4; r++)
        acc[a][b][r] = 0.f;

    const unsigned sbA = smem_u32(sA);
    const unsigned a_off =
        (((unsigned)((lane & 7) + ((lane >> 3) & 1) * 8)) * XROW_ + (unsigned)(lane >> 4) * 8) * 2;
    const unsigned short* brow = sB + (wn * 16 + (lane >> 2)) * XROW_ + (lane & 3) * 2;

    #pragma unroll 4
    for (int ki = 0; ki < 16; ki++) {
        const int k0 = ki * 16;
        unsigned av[4][4];
        #pragma unroll
        for (int mt = 0; mt < 4; mt++)
            ldsm4(av[mt], sbA + a_off + (unsigned)((wm * 64 + mt * 16) * XROW_ + k0) * 2);
        #pragma unroll
        for (int nt = 0; nt < 2; nt++) {
            unsigned b0 = *(const unsigned*)(brow + nt * 8 * XROW_ + k0);
            unsigned b1 = *(const unsigned*)(brow + nt * 8 * XROW_ + k0 + 8);
            #pragma unroll
            for (int mt = 0; mt < 4; mt++) mma_bf16(acc[mt][nt], av[mt], b0, b1);
        }
    }

    float ex[4][2][4];
    #pragma unroll
    for (int a = 0; a < 4; a++) for (int b = 0; b < 2; b++) for (int r = 0; r < 4; r++)
        ex[a][b][r] = __shfl_xor_sync(0xffffffffu, acc[a][b][r], 1);

    if (!(lane & 1)) {
        #pragma unroll
        for (int mt = 0; mt < 4; mt++) {
            #pragma unroll
            for (int nt = 0; nt < 2; nt++) {
                const int cn = n0 + wn * 16 + nt * 8 + (lane & 3) * 2;
                if (cn >= G4_) continue;
                const float4 bi = *(const float4*)&g_biasI0[which][cn];
                #pragma unroll
                for (int half = 0; half < 2; half++) {
                    const int row = m0 + wm * 64 + mt * 16 + half * 8 + (lane >> 2);
                    float4 o4;
                    o4.x = acc[mt][nt][half * 2 + 0] + bi.x;
                    o4.y = acc[mt][nt][half * 2 + 1] + bi.y;
                    o4.z = ex[mt][nt][half * 2 + 0] + bi.z;
                    o4.w = ex[mt][nt][half * 2 + 1] + bi.w;
                    *(float4*)&g_pre[which][(size_t)row * G4_ + cn] = o4;
                }
            }
        }
    }
}

// ---------------- persistent scan (unchanged from R12 best) ----------------
__device__ __forceinline__ void gbar(int s) {
    __syncthreads();
    if (threadIdx.x == 0) {
        asm volatile("red.release.gpu.global.add.u32 [%0], %1;"
            :: "l"(&g_cnt), "r"(1u) : "memory");
        const unsigned target = (unsigned)SCANB_ * (unsigned)(s + 1);
        unsigned v;
        do {
            asm volatile("ld.acquire.gpu.global.u32 %0, [%1];"
                : "=r"(v) : "l"(&g_cnt) : "memory");
        } while (v < target);
    }
    __syncthreads();
}

__device__ __forceinline__ void gemm_w(const unsigned short* wrow, unsigned abase,
                                       float acc[4]) {
    #pragma unroll 4
    for (int ki = 0; ki < NKI_; ki++) {
        const int k0 = ki * 16;
        unsigned av[4];
        ldsm4(av, abase + (unsigned)k0 * 2);
        unsigned b0 = *(const unsigned*)(wrow + k0);
        unsigned b1 = *(const unsigned*)(wrow + k0 + 8);
        mma_bf16(acc, av, b0, b1);
    }
}

__global__ __launch_bounds__(256) void scan_kernel() {
    extern __shared__ __align__(16) unsigned short ssm[];
    unsigned short* sWa = ssm + 2 * 32 * SROW_;
    unsigned short* sWb = ssm + 3 * 32 * SROW_;
    const unsigned sbase = smem_u32(ssm);
    const unsigned mbarA = sbase + 4u * BUFB_;
    const unsigned mbarB = sbase + 4u * BUFB_ + 16u;
    const int bid = blockIdx.x;
    const int layer = (bid >= 66) ? 1 : 0;
    const int tile = layer ? bid - 66 : bid;
    const int tid = threadIdx.x, lane = tid & 31, warp = tid >> 5;
    const int mt = warp >> 2, nt = warp & 3;
    const int m_off = mt * 16;
    const int nw = tile * 32 + nt * 8;
    const int cn = nw + (lane & 3) * 2;
    const int j = cn >> 2;
    const bool epi = (!(lane & 1)) && (cn < G4_);
    const int b0r = m_off + (lane >> 2);
    const int b1r = b0r + 8;
    const size_t woff = (size_t)tile * 32 * SROW_;

    if (tid == 0) {
        asm volatile("mbarrier.init.shared.b64 [%0], %1;" :: "r"(mbarA), "r"(1u) : "memory");
        asm volatile("mbarrier.init.shared.b64 [%0], %1;" :: "r"(mbarB), "r"(1u) : "memory");
    }
    __syncthreads();

    const unsigned a_off =
        (((unsigned)((lane & 7) + ((lane >> 3) & 1) * 8)) * SROW_ + (unsigned)(lane >> 4) * 8) * 2;
    const unsigned a0base = sbase + (unsigned)m_off * SROW_ * 2 + a_off;
    const unsigned a1base = sbase + BUFB_ + (unsigned)m_off * SROW_ * 2 + a_off;
    const unsigned short* wrowA = sWa + (nt * 8 + (lane >> 2)) * SROW_ + (lane & 3) * 2;
    const unsigned short* wrowB = sWb + (nt * 8 + (lane >> 2)) * SROW_ + (lane & 3) * 2;

    float creg0 = 0.f, creg1 = 0.f;

    for (int s = 0; s <= 128; s++) {
        if (tid == 0) {
            if (layer == 0) {
                unsigned tx = BUFB_ + ((s == 0 || s == 64) ? BUFB_ : 0u);
                mbar_expect_tx(mbarA, tx);
                bulk_cp(sbase, g_hb[0][(s & 1) ^ 1], BUFB_, mbarA);
                if (s == 0)  bulk_cp(sbase + 2u * BUFB_, g_Wb[0] + woff, BUFB_, mbarA);
                if (s == 64) bulk_cp(sbase + 2u * BUFB_, g_Wb[3] + woff, BUFB_, mbarA);
            } else {
                const bool wslot = (s == 0 || s == 65);
                unsigned txA = BUFB_ + (wslot ? BUFB_ : 0u);
                unsigned txB = BUFB_ + (wslot ? BUFB_ : 0u);
                mbar_expect_tx(mbarA, txA);
                mbar_expect_tx(mbarB, txB);
                bulk_cp(sbase, g_hb[0][(s & 1) ^ 1], BUFB_, mbarA);
                bulk_cp(sbase + BUFB_, g_hb[1][s & 1], BUFB_, mbarB);
                if (s == 0) {
                    bulk_cp(sbase + 2u * BUFB_, g_Wb[1] + woff, BUFB_, mbarA);
                    bulk_cp(sbase + 3u * BUFB_, g_Wb[2] + woff, BUFB_, mbarB);
                }
                if (s == 65) {
                    bulk_cp(sbase + 2u * BUFB_, g_Wb[4] + woff, BUFB_, mbarA);
                    bulk_cp(sbase + 3u * BUFB_, g_Wb[5] + woff, BUFB_, mbarB);
                }
            }
        }

        const bool active = layer ? (s >= 1) : (s <= 127);
        const int z = s - 1;
        const int sel = layer ? (z >= 64 ? 1 : 0) : (s >= 64 ? 1 : 0);
        const int tstep = layer ? (sel ? z - 64 : z) : (sel ? s - 64 : s);

        float4 add0, add1;
        if (active && epi) {
            if (layer) {
                add0 = *(const float4*)&g_biasI1[sel][cn];
                add1 = add0;
            } else {
                add0 = *(const float4*)&g_pre[sel][(size_t)(tstep * B_ + b0r) * G4_ + cn];
                add1 = *(const float4*)&g_pre[sel][(size_t)(tstep * B_ + b1r) * G4_ + cn];
            }
        }

        mbar_wait(mbarA, s & 1);

        if (active) {
            float acc[4] = {0.f, 0.f, 0.f, 0.f};
            if (layer) {
                gemm_w(wrowA, a0base, acc);
                mbar_wait(mbarB, s & 1);
                gemm_w(wrowB, a1base, acc);
            } else {
                gemm_w(wrowA, a0base, acc);
            }
            float ex[4];
            #pragma unroll
            for (int r = 0; r < 4; r++)
                ex[r] = __shfl_xor_sync(0xffffffffu, acc[r], 1);

            if (epi) {
                __nv_bfloat16* hout = layer ? g_hb[1][(s & 1) ^ 1] : g_hb[0][s & 1];
                {
                    float iv = sigf(acc[0] + add0.x);
                    float fv = sigf(acc[1] + add0.y);
                    float gv = tanh_f(ex[0] + add0.z);
                    float ov = sigf(ex[1] + add0.w);
                    creg0 = fv * creg0 + iv * gv;
                    float h = ov * tanh_f(creg0);
                    __nv_bfloat16 hb = __float2bfloat16(h);
                    hout[b0r * SROW_ + j] = hb;
                    if (layer && sel) g_histb[(size_t)(tstep * B_ + b0r) * NK_ + j] = hb;
                }
                {
                    float iv = sigf(acc[2] + add1.x);
                    float fv = sigf(acc[3] + add1.y);
                    float gv = tanh_f(ex[2] + add1.z);
                    float ov = sigf(ex[3] + add1.w);
                    creg1 = fv * creg1 + iv * gv;
                    float h = ov * tanh_f(creg1);
                    __nv_bfloat16 hb = __float2bfloat16(h);
                    hout[b1r * SROW_ + j] = hb;
                    if (layer && sel) g_histb[(size_t)(tstep * B_ + b1r) * NK_ + j] = hb;
                }
            }
        } else if (layer) {
            mbar_wait(mbarB, s & 1);
        }
        if (s < 128) gbar(s);
    }
}

// ---------------- fused vocab projection + CE: N=128, 3-buffer single-sync pipeline ----------------
// grid 250 blocks x 256 thr. Block owns 128-vocab N-tile (resident bf16 in smem),
// loops 16 M-tiles; A chunks triple-buffered, ONE sync per chunk, cross-tile prefetch.
#define SROWCE_ 536
__global__ __launch_bounds__(256) void ce2(const float* __restrict__ Wout,
                                           const float* __restrict__ bout,
                                           const int* __restrict__ y) {
    extern __shared__ __align__(16) unsigned short csm[];
    unsigned short* sB = csm;                       // [128][SROWCE_] bf16 Wout tile
    unsigned short* sA = csm + 128 * SROWCE_;       // 3 x [128][CROW2_]
    const int tid = threadIdx.x, lane = tid & 31, warp = tid >> 5;
    const int bx = blockIdx.x;

    // ---- load + convert B tile fp32 -> bf16 (once) ----
    {
        const int r = tid >> 1;
        const int n = bx * 128 + r;
        const float4* src = (const float4*)(Wout + (size_t)n * HID_);
        unsigned short* drow = sB + r * SROWCE_;
        for (int q = (tid & 1); q < 129; q += 2) {
            float4 v = src[q];
            ushort4 o;
            o.x = bfc(v.x); o.y = bfc(v.y); o.z = bfc(v.z); o.w = bfc(v.w);
            *(ushort4*)(drow + q * 4) = o;
        }
        if (tid & 1) {   // zero pad cols 516..527
            ushort4 zz = make_ushort4(0, 0, 0, 0);
            *(ushort4*)(drow + 516) = zz;
            *(ushort4*)(drow + 520) = zz;
            *(ushort4*)(drow + 524) = zz;
        }
    }

    const int wm = warp >> 2, wn = warp & 3;
    const unsigned sbA = smem_u32(sA);
    const unsigned bufB = (unsigned)128 * CROW2_ * 2;
    const unsigned a_off =
        (((unsigned)((lane & 7) + ((lane >> 3) & 1) * 8)) * CROW2_ + (unsigned)(lane >> 4) * 8) * 2;
    const unsigned short* brow = sB + (wn * 32 + (lane >> 2)) * SROWCE_ + (lane & 3) * 2;

    const int sr = tid >> 1, sh = tid & 1;

    // stage chunk C of m-tile MT into buffer BUF (0..2)
    #define CSTAGE(MT, C, BUF) do { \
        const size_t srcbase = (size_t)((MT) * 128 + sr) * NK_ + (C) * 64; \
        unsigned dstr = smem_u32(sA) + ((unsigned)(BUF)) * bufB \
                      + (unsigned)(sr * CROW2_) * 2; \
        if ((C) < 8) { \
            const char* s0 = (const char*)(g_histb + srcbase + sh * 32); \
            unsigned d0 = dstr + (unsigned)(sh * 32) * 2; \
            asm volatile("cp.async.cg.shared.global [%0], [%1], 16;" :: "r"(d0), "l"(s0)); \
            asm volatile("cp.async.cg.shared.global [%0], [%1], 16;" :: "r"(d0 + 16), "l"(s0 + 16)); \
            asm volatile("cp.async.cg.shared.global [%0], [%1], 16;" :: "r"(d0 + 32), "l"(s0 + 32)); \
            asm volatile("cp.async.cg.shared.global [%0], [%1], 16;" :: "r"(d0 + 48), "l"(s0 + 48)); \
        } else { \
            const char* s0 = (const char*)(g_histb + srcbase + sh * 8); \
            unsigned d0 = dstr + (unsigned)(sh * 8) * 2; \
            asm volatile("cp.async.cg.shared.global [%0], [%1], 16;" :: "r"(d0), "l"(s0)); \
        } \
        asm volatile("cp.async.commit_group;"); \
    } while (0)

    __syncthreads();   // sB ready

    CSTAGE(0, 0, 0);   // prime the pipeline
    int buf = 0;       // buffer holding the chunk about to be consumed

    for (int mt = 0; mt < 16; mt++) {
        float acc[4][4][4];
        #pragma unroll
        for (int a = 0; a < 4; a++) for (int b = 0; b < 4; b++) for (int r = 0; r < 4; r++)
            acc[a][b][r] = 0.f;

        for (int c = 0; c < 9; c++) {
            int nb = buf + 1; if (nb == 3) nb = 0;
            const bool last = (mt == 15) && (c == 8);
            if (!last) {
                if (c < 8) CSTAGE(mt, c + 1, nb);
                else       CSTAGE(mt + 1, 0, nb);   // cross-tile prefetch
                asm volatile("cp.async.wait_group 1;");
            } else {
                asm volatile("cp.async.wait_group 0;");
            }
            __syncthreads();   // single sync per chunk (3 buffers make trailing sync redundant)

            const unsigned chbase = sbA + ((unsigned)buf) * bufB + a_off;
            const int nk16 = (c == 8) ? 1 : 4;
            for (int kk = 0; kk < nk16; kk++) {
                unsigned av[4][4];
                #pragma unroll
                for (int q = 0; q < 4; q++)
                    ldsm4(av[q], chbase + (unsigned)((wm * 64 + q * 16) * CROW2_ + kk * 16) * 2);
                const int k0 = c * 64 + kk * 16;
                #pragma unroll
                for (int nt = 0; nt < 4; nt++) {
                    unsigned b0 = *(const unsigned*)(brow + nt * 8 * SROWCE_ + k0);
                    unsigned b1 = *(const unsigned*)(brow + nt * 8 * SROWCE_ + k0 + 8);
                    #pragma unroll
                    for (int q = 0; q < 4; q++) mma_bf16(acc[q][nt], av[q], b0, b1);
                }
            }
            buf = nb;
        }

        // epilogue for this m-tile (overlaps the prefetched next-tile chunk transfer)
        #pragma unroll
        for (int q = 0; q < 4; q++) {
            const int r0 = mt * 128 + wm * 64 + q * 16 + (lane >> 2);
            const int r1 = r0 + 8;
            const int tg0 = y[r0 + 32];
            const int tg1 = y[r1 + 32];
            float s0 = 0.f, s1 = 0.f;
            #pragma unroll
            for (int nt = 0; nt < 4; nt++) {
                const int cnv = bx * 128 + wn * 32 + nt * 8 + (lane & 3) * 2;
                const float2 bo = *(const float2*)&bout[cnv];
                float l0 = acc[q][nt][0] + bo.x;
                float l1 = acc[q][nt][1] + bo.y;
                float l2 = acc[q][nt][2] + bo.x;
                float l3 = acc[q][nt][3] + bo.y;
                s0 += __expf(l0) + __expf(l1);
                s1 += __expf(l2) + __expf(l3);
                if (cnv == tg0)     atomicAdd(&g_tgt[r0], l0);
                if (cnv + 1 == tg0) atomicAdd(&g_tgt[r0], l1);
                if (cnv == tg1)     atomicAdd(&g_tgt[r1], l2);
                if (cnv + 1 == tg1) atomicAdd(&g_tgt[r1], l3);
            }
            s0 += __shfl_xor_sync(0xffffffffu, s0, 1);
            s0 += __shfl_xor_sync(0xffffffffu, s0, 2);
            s1 += __shfl_xor_sync(0xffffffffu, s1, 1);
            s1 += __shfl_xor_sync(0xffffffffu, s1, 2);
            if (!(lane & 3)) {
                atomicAdd(&g_sumexp[r0], s0);
                atomicAdd(&g_sumexp[r1], s1);
            }
        }
    }
    #undef CSTAGE
}

// ---------------- final reduction ----------------
__global__ __launch_bounds__(256) void finalize_kernel(float* out) {
    __shared__ float sm[256];
    float s = 0.f;
    for (int r = threadIdx.x; r < ROWS_; r += 256)
        s += logf(g_sumexp[r]) - g_tgt[r];
    sm[threadIdx.x] = s;
    __syncthreads();
    for (int st = 128; st; st >>= 1) {
        if (threadIdx.x < st) sm[threadIdx.x] += sm[threadIdx.x + st];
        __syncthreads();
    }
    if (threadIdx.x == 0) out[0] = sm[0] / 32.f;
}

// ---------------- host launcher ----------------
extern "C" void kernel_launch(void* const* d_in, const int* in_sizes, int n_in,
                              void* d_out, int out_size)
{
    (void)in_sizes; (void)n_in; (void)out_size;
    const int*   x        = (const int*)  d_in[0];
    const int*   y        = (const int*)  d_in[1];
    const float* encemb   = (const float*)d_in[2];
    const float* decemb   = (const float*)d_in[3];
    const float* enc_Wih0 = (const float*)d_in[4];
    const float* enc_Whh0 = (const float*)d_in[5];
    const float* enc_bih0 = (const float*)d_in[6];
    const float* enc_bhh0 = (const float*)d_in[7];
    const float* enc_Wih1 = (const float*)d_in[8];
    const float* enc_Whh1 = (const float*)d_in[9];
    const float* enc_bih1 = (const float*)d_in[10];
    const float* enc_bhh1 = (const float*)d_in[11];
    const float* dec_Wih0 = (const float*)d_in[12];
    const float* dec_Whh0 = (const float*)d_in[13];
    const float* dec_bih0 = (const float*)d_in[14];
    const float* dec_bhh0 = (const float*)d_in[15];
    const float* dec_Wih1 = (const float*)d_in[16];
    const float* dec_Whh1 = (const float*)d_in[17];
    const float* dec_bih1 = (const float*)d_in[18];
    const float* dec_bhh1 = (const float*)d_in[19];
    const float* Wout     = (const float*)d_in[20];
    const float* bout     = (const float*)d_in[21];
    float* out = (float*)d_out;

    const int PRE_SMEM  = (128 + 64) * XROW_ * 2;                     // 101,376
    const int SCAN_SMEM = 4 * BUFB_ + 32;                             // 137,248
    const int CE_SMEM   = 128 * SROWCE_ * 2 + 3 * 128 * CROW2_ * 2;   // 192,512
    cudaFuncSetAttribute(pre_gemm,    cudaFuncAttributeMaxDynamicSharedMemorySize, PRE_SMEM);
    cudaFuncSetAttribute(scan_kernel, cudaFuncAttributeMaxDynamicSharedMemorySize, SCAN_SMEM);
    cudaFuncSetAttribute(ce2,         cudaFuncAttributeMaxDynamicSharedMemorySize, CE_SMEM);

    // launch order: harness emits 2 launches first; ce2 (our #3) lands at
    // global #5 where ncu -s 5 -c 1 samples.
    ConvArgs ca;
    ca.w[0] = enc_Whh0; ca.w[1] = enc_Wih1; ca.w[2] = enc_Whh1;
    ca.w[3] = dec_Whh0; ca.w[4] = dec_Wih1; ca.w[5] = dec_Whh1;
    ca.b[0] = enc_bih0; ca.b[1] = enc_bhh0; ca.b[2] = dec_bih0; ca.b[3] = dec_bhh0;
    ca.b[4] = enc_bih1; ca.b[5] = enc_bhh1; ca.b[6] = dec_bih1; ca.b[7] = dec_bhh1;
    const int GC = (NPAD_ * (SROW_ / 2) + 255) / 256;
    conv_setup<<<dim3(GC, 7), 256>>>(ca);                                    // 0

    pre_gemm<<<dim3(33, 32), 256, PRE_SMEM>>>(x, y, encemb, decemb,          // 1
                                              enc_Wih0, dec_Wih0);

    scan_kernel<<<SCANB_, 256, SCAN_SMEM>>>();                               // 2

    ce2<<<250, 256, CE_SMEM>>>(Wout, bout, y);                               // 3  <- ncu sample

    finalize_kernel<<<1, 256>>>(out);                                        // 4
}

// round 17
// speedup vs baseline: 1.1711x; 1.0852x over previous
#include <cuda_runtime.h>
#include <cuda_bf16.h>
#include <math.h>

#define B_    32
#define EMB_  256
#define HID_  516
#define G4_   2064     // 4*HID_
#define V_    32000
#define ROWS_ 2048     // 64*32 decoder rows
#define NK_   528      // K padded to multiple of 16 (hist layout)
#define NKI_  33       // k-iterations of 16
#define SROW_ 536      // row stride (u16) for h/W tiles, ldmatrix conflict-free
#define XROW_ 264      // smem row stride (u16) for K=256 tiles
#define NPAD_ 2112     // gate-col dim padded (66 tiles * 32)
#define SCANB_ 132     // scan blocks (<=148, all co-resident)
#define CROW2_ 72      // CE A-chunk row stride (u16), 64 cols + pad
#define BUFB_  34304   // one staged buffer: 32*SROW_*2 bytes

// ---------------- scratch (static device globals; no allocation) ----------------
__device__ __nv_bfloat16 g_Wb[6][NPAD_ * SROW_];      // scan weights bf16, PADDED rows
__device__ float         g_pre[2][ROWS_ * G4_];       // input proj + bias, gate-interleaved
__device__ __nv_bfloat16 g_hb[2][2][B_ * SROW_];      // h state [layer][buf], PADDED rows
__device__ __nv_bfloat16 g_histb[ROWS_ * NK_ + 64];   // decoder h1 history bf16 (+pad)
__device__ float         g_biasI0[2][G4_];            // layer0 bias (folded into pre)
__device__ float         g_biasI1[2][G4_];            // layer1 bias
__device__ float         g_sumexp[ROWS_];
__device__ float         g_tgt[ROWS_];
__device__ unsigned      g_cnt;                       // grid barrier arrivals (monotonic)

// ---------------- helpers ----------------
__device__ __forceinline__ unsigned smem_u32(const void* p) {
    return (unsigned)__cvta_generic_to_shared(p);
}
__device__ __forceinline__ void ldsm4(unsigned a[4], unsigned addr) {
    asm volatile("ldmatrix.sync.aligned.m8n8.x4.shared.b16 {%0,%1,%2,%3}, [%4];"
        : "=r"(a[0]), "=r"(a[1]), "=r"(a[2]), "=r"(a[3]) : "r"(addr));
}
__device__ __forceinline__ void mma_bf16(float c[4], const unsigned a[4], unsigned b0, unsigned b1) {
    asm volatile("mma.sync.aligned.m16n8k16.row.col.f32.bf16.bf16.f32 "
        "{%0,%1,%2,%3},{%4,%5,%6,%7},{%8,%9},{%0,%1,%2,%3};"
        : "+f"(c[0]), "+f"(c[1]), "+f"(c[2]), "+f"(c[3])
        : "r"(a[0]), "r"(a[1]), "r"(a[2]), "r"(a[3]), "r"(b0), "r"(b1));
}
__device__ __forceinline__ float sigf(float x) {
    return __fdividef(1.f, 1.f + __expf(-x));
}
__device__ __forceinline__ float tanh_f(float x) {
    float t = __expf(2.f * x);
    return __fdividef(t - 1.f, t + 1.f);
}
__device__ __forceinline__ unsigned short bfc(float v) {
    return __bfloat16_as_ushort(__float2bfloat16(v));
}
__device__ __forceinline__ void bulk_cp(unsigned dst, const void* src, unsigned bytes,
                                        unsigned mbar) {
    asm volatile(
        "cp.async.bulk.shared::cluster.global.mbarrier::complete_tx::bytes [%0], [%1], %2, [%3];"
        :: "r"(dst), "l"(src), "r"(bytes), "r"(mbar) : "memory");
}
__device__ __forceinline__ void mbar_expect_tx(unsigned mbar, unsigned bytes) {
    asm volatile("mbarrier.arrive.expect_tx.shared.b64 _, [%0], %1;"
        :: "r"(mbar), "r"(bytes) : "memory");
}
__device__ __forceinline__ void mbar_wait(unsigned mbar, unsigned parity) {
    unsigned done;
    asm volatile(
        "{\n\t.reg .pred p;\n\t"
        "mbarrier.try_wait.parity.acquire.cta.shared::cta.b64 p, [%1], %2;\n\t"
        "selp.b32 %0, 1, 0, p;\n\t}"
        : "=r"(done) : "r"(mbar), "r"(parity) : "memory");
    while (!done) {
        asm volatile(
            "{\n\t.reg .pred p;\n\t"
            "mbarrier.try_wait.parity.acquire.cta.shared::cta.b64 p, [%1], %2, 0x989680;\n\t"
            "selp.b32 %0, 1, 0, p;\n\t}"
            : "=r"(done) : "r"(mbar), "r"(parity) : "memory");
    }
}

// ---------------- combo: weight conversion (y<6) + setup (y==6) ----------------
struct ConvArgs {
    const float* w[6];
    const float* b[8];
};

__global__ __launch_bounds__(256) void conv_setup(ConvArgs a) {
    if (blockIdx.y < 6) {
        const int slot = blockIdx.y;
        const float* __restrict__ src = a.w[slot];
        int idx = blockIdx.x * blockDim.x + threadIdx.x;
        if (idx >= NPAD_ * (SROW_ / 2)) return;
        int n = idx / (SROW_ / 2), q = idx - n * (SROW_ / 2), k = q * 2;
        float2 v = make_float2(0.f, 0.f);
        if (n < G4_ && k < HID_) {
            int j = n >> 2, g = n & 3;
            v = *(const float2*)&src[(size_t)(g * HID_ + j) * HID_ + k];
        }
        unsigned o = ((unsigned)bfc(v.y) << 16) | (unsigned)bfc(v.x);
        *(unsigned*)&g_Wb[slot][n * SROW_ + k] = o;
        return;
    }
    const int stride = gridDim.x * blockDim.x;
    const int i0 = blockIdx.x * blockDim.x + threadIdx.x;
    const __nv_bfloat16 z = __float2bfloat16(0.f);
    for (int i = i0; i < B_ * SROW_; i += stride) {
        g_hb[0][0][i] = z; g_hb[0][1][i] = z;
        g_hb[1][0][i] = z; g_hb[1][1][i] = z;
    }
    for (int i = i0; i < ROWS_; i += stride) { g_sumexp[i] = 0.f; g_tgt[i] = 0.f; }
    for (int i = i0; i < ROWS_ * 12; i += stride) {
        int r = i / 12, k = HID_ + i - r * 12;
        g_histb[r * NK_ + k] = z;
    }
    for (int t = i0; t < 2 * G4_; t += stride) {
        int sel = t / G4_, n = t - sel * G4_;
        int j = n >> 2, g = n & 3;
        g_biasI0[sel][n] = (sel ? a.b[2] : a.b[0])[g * HID_ + j]
                         + (sel ? a.b[3] : a.b[1])[g * HID_ + j];
        g_biasI1[sel][n] = (sel ? a.b[6] : a.b[4])[g * HID_ + j]
                         + (sel ? a.b[7] : a.b[5])[g * HID_ + j];
    }
    if (blockIdx.x == 0 && threadIdx.x == 0) g_cnt = 0u;
}

// ---------------- fused input projection (unchanged) ----------------
__global__ __launch_bounds__(256) void pre_gemm(
    const int* __restrict__ x, const int* __restrict__ y,
    const float* __restrict__ encemb, const float* __restrict__ decemb,
    const float* __restrict__ Wih0e, const float* __restrict__ Wih0d)
{
    extern __shared__ __align__(16) unsigned short psm[];
    unsigned short* sA = psm;
    unsigned short* sB = psm + 128 * XROW_;
    const int tid = threadIdx.x, lane = tid & 31, warp = tid >> 5;
    const int which = blockIdx.y >> 4, mtile = blockIdx.y & 15;
    const int m0 = mtile * 128, n0 = blockIdx.x * 64;
    const int* idx = which ? y : x;
    const float* emb = which ? decemb : encemb;
    const float* Wsrc = which ? Wih0d : Wih0e;

    {
        const int r = tid >> 1, h = tid & 1;
        const int tok = idx[m0 + r];
        const float4* es = (const float4*)(emb + (size_t)tok * EMB_ + h * 128);
        unsigned short* drow = sA + r * XROW_ + h * 128;
        #pragma unroll
        for (int q = 0; q < 32; q++) {
            float4 v = es[q];
            ushort4 o;
            o.x = bfc(v.x); o.y = bfc(v.y); o.z = bfc(v.z); o.w = bfc(v.w);
            *(ushort4*)(drow + q * 4) = o;
        }
    }
    {
        const int rb = tid >> 2, qt = tid & 3;
        const int n = n0 + rb;
        unsigned short* drow = sB + rb * XROW_ + qt * 64;
        if (n < G4_) {
            const int j = n >> 2, g = n & 3;
            const float4* ws = (const float4*)(Wsrc + (size_t)(g * HID_ + j) * EMB_ + qt * 64);
            #pragma unroll
            for (int q = 0; q < 16; q++) {
                float4 v = ws[q];
                ushort4 o;
                o.x = bfc(v.x); o.y = bfc(v.y); o.z = bfc(v.z); o.w = bfc(v.w);
                *(ushort4*)(drow + q * 4) = o;
            }
        } else {
            ushort4 zz = make_ushort4(0, 0, 0, 0);
            #pragma unroll
            for (int q = 0; q < 16; q++) *(ushort4*)(drow + q * 4) = zz;
        }
    }
    __syncthreads();

    const int wm = warp >> 2, wn = warp & 3;
    float acc[4][2][4];
    #pragma unroll
    for (int a = 0; a < 4; a++) for (int b = 0; b < 2; b++) for (int r = 0; r < 4; r++)
        acc[a][b][r] = 0.f;

    const unsigned sbA = smem_u32(sA);
    const unsigned a_off =
        (((unsigned)((lane & 7) + ((lane >> 3) & 1) * 8)) * XROW_ + (unsigned)(lane >> 4) * 8) * 2;
    const unsigned short* brow = sB + (wn * 16 + (lane >> 2)) * XROW_ + (lane & 3) * 2;

    #pragma unroll 4
    for (int ki = 0; ki < 16; ki++) {
        const int k0 = ki * 16;
        unsigned av[4][4];
        #pragma unroll
        for (int mt = 0; mt < 4; mt++)
            ldsm4(av[mt], sbA + a_off + (unsigned)((wm * 64 + mt * 16) * XROW_ + k0) * 2);
        #pragma unroll
        for (int nt = 0; nt < 2; nt++) {
            unsigned b0 = *(const unsigned*)(brow + nt * 8 * XROW_ + k0);
            unsigned b1 = *(const unsigned*)(brow + nt * 8 * XROW_ + k0 + 8);
            #pragma unroll
            for (int mt = 0; mt < 4; mt++) mma_bf16(acc[mt][nt], av[mt], b0, b1);
        }
    }

    float ex[4][2][4];
    #pragma unroll
    for (int a = 0; a < 4; a++) for (int b = 0; b < 2; b++) for (int r = 0; r < 4; r++)
        ex[a][b][r] = __shfl_xor_sync(0xffffffffu, acc[a][b][r], 1);

    if (!(lane & 1)) {
        #pragma unroll
        for (int mt = 0; mt < 4; mt++) {
            #pragma unroll
            for (int nt = 0; nt < 2; nt++) {
                const int cn = n0 + wn * 16 + nt * 8 + (lane & 3) * 2;
                if (cn >= G4_) continue;
                const float4 bi = *(const float4*)&g_biasI0[which][cn];
                #pragma unroll
                for (int half = 0; half < 2; half++) {
                    const int row = m0 + wm * 64 + mt * 16 + half * 8 + (lane >> 2);
                    float4 o4;
                    o4.x = acc[mt][nt][half * 2 + 0] + bi.x;
                    o4.y = acc[mt][nt][half * 2 + 1] + bi.y;
                    o4.z = ex[mt][nt][half * 2 + 0] + bi.z;
                    o4.w = ex[mt][nt][half * 2 + 1] + bi.w;
                    *(float4*)&g_pre[which][(size_t)row * G4_ + cn] = o4;
                }
            }
        }
    }
}

// ---------------- persistent scan (unchanged from R12 best) ----------------
__device__ __forceinline__ void gbar(int s) {
    __syncthreads();
    if (threadIdx.x == 0) {
        asm volatile("red.release.gpu.global.add.u32 [%0], %1;"
            :: "l"(&g_cnt), "r"(1u) : "memory");
        const unsigned target = (unsigned)SCANB_ * (unsigned)(s + 1);
        unsigned v;
        do {
            asm volatile("ld.acquire.gpu.global.u32 %0, [%1];"
                : "=r"(v) : "l"(&g_cnt) : "memory");
        } while (v < target);
    }
    __syncthreads();
}

__device__ __forceinline__ void gemm_w(const unsigned short* wrow, unsigned abase,
                                       float acc[4]) {
    #pragma unroll 4
    for (int ki = 0; ki < NKI_; ki++) {
        const int k0 = ki * 16;
        unsigned av[4];
        ldsm4(av, abase + (unsigned)k0 * 2);
        unsigned b0 = *(const unsigned*)(wrow + k0);
        unsigned b1 = *(const unsigned*)(wrow + k0 + 8);
        mma_bf16(acc, av, b0, b1);
    }
}

__global__ __launch_bounds__(256) void scan_kernel() {
    extern __shared__ __align__(16) unsigned short ssm[];
    unsigned short* sWa = ssm + 2 * 32 * SROW_;
    unsigned short* sWb = ssm + 3 * 32 * SROW_;
    const unsigned sbase = smem_u32(ssm);
    const unsigned mbarA = sbase + 4u * BUFB_;
    const unsigned mbarB = sbase + 4u * BUFB_ + 16u;
    const int bid = blockIdx.x;
    const int layer = (bid >= 66) ? 1 : 0;
    const int tile = layer ? bid - 66 : bid;
    const int tid = threadIdx.x, lane = tid & 31, warp = tid >> 5;
    const int mt = warp >> 2, nt = warp & 3;
    const int m_off = mt * 16;
    const int nw = tile * 32 + nt * 8;
    const int cn = nw + (lane & 3) * 2;
    const int j = cn >> 2;
    const bool epi = (!(lane & 1)) && (cn < G4_);
    const int b0r = m_off + (lane >> 2);
    const int b1r = b0r + 8;
    const size_t woff = (size_t)tile * 32 * SROW_;

    if (tid == 0) {
        asm volatile("mbarrier.init.shared.b64 [%0], %1;" :: "r"(mbarA), "r"(1u) : "memory");
        asm volatile("mbarrier.init.shared.b64 [%0], %1;" :: "r"(mbarB), "r"(1u) : "memory");
    }
    __syncthreads();

    const unsigned a_off =
        (((unsigned)((lane & 7) + ((lane >> 3) & 1) * 8)) * SROW_ + (unsigned)(lane >> 4) * 8) * 2;
    const unsigned a0base = sbase + (unsigned)m_off * SROW_ * 2 + a_off;
    const unsigned a1base = sbase + BUFB_ + (unsigned)m_off * SROW_ * 2 + a_off;
    const unsigned short* wrowA = sWa + (nt * 8 + (lane >> 2)) * SROW_ + (lane & 3) * 2;
    const unsigned short* wrowB = sWb + (nt * 8 + (lane >> 2)) * SROW_ + (lane & 3) * 2;

    float creg0 = 0.f, creg1 = 0.f;

    for (int s = 0; s <= 128; s++) {
        if (tid == 0) {
            if (layer == 0) {
                unsigned tx = BUFB_ + ((s == 0 || s == 64) ? BUFB_ : 0u);
                mbar_expect_tx(mbarA, tx);
                bulk_cp(sbase, g_hb[0][(s & 1) ^ 1], BUFB_, mbarA);
                if (s == 0)  bulk_cp(sbase + 2u * BUFB_, g_Wb[0] + woff, BUFB_, mbarA);
                if (s == 64) bulk_cp(sbase + 2u * BUFB_, g_Wb[3] + woff, BUFB_, mbarA);
            } else {
                const bool wslot = (s == 0 || s == 65);
                unsigned txA = BUFB_ + (wslot ? BUFB_ : 0u);
                unsigned txB = BUFB_ + (wslot ? BUFB_ : 0u);
                mbar_expect_tx(mbarA, txA);
                mbar_expect_tx(mbarB, txB);
                bulk_cp(sbase, g_hb[0][(s & 1) ^ 1], BUFB_, mbarA);
                bulk_cp(sbase + BUFB_, g_hb[1][s & 1], BUFB_, mbarB);
                if (s == 0) {
                    bulk_cp(sbase + 2u * BUFB_, g_Wb[1] + woff, BUFB_, mbarA);
                    bulk_cp(sbase + 3u * BUFB_, g_Wb[2] + woff, BUFB_, mbarB);
                }
                if (s == 65) {
                    bulk_cp(sbase + 2u * BUFB_, g_Wb[4] + woff, BUFB_, mbarA);
                    bulk_cp(sbase + 3u * BUFB_, g_Wb[5] + woff, BUFB_, mbarB);
                }
            }
        }

        const bool active = layer ? (s >= 1) : (s <= 127);
        const int z = s - 1;
        const int sel = layer ? (z >= 64 ? 1 : 0) : (s >= 64 ? 1 : 0);
        const int tstep = layer ? (sel ? z - 64 : z) : (sel ? s - 64 : s);

        float4 add0, add1;
        if (active && epi) {
            if (layer) {
                add0 = *(const float4*)&g_biasI1[sel][cn];
                add1 = add0;
            } else {
                add0 = *(const float4*)&g_pre[sel][(size_t)(tstep * B_ + b0r) * G4_ + cn];
                add1 = *(const float4*)&g_pre[sel][(size_t)(tstep * B_ + b1r) * G4_ + cn];
            }
        }

        mbar_wait(mbarA, s & 1);

        if (active) {
            float acc[4] = {0.f, 0.f, 0.f, 0.f};
            if (layer) {
                gemm_w(wrowA, a0base, acc);
                mbar_wait(mbarB, s & 1);
                gemm_w(wrowB, a1base, acc);
            } else {
                gemm_w(wrowA, a0base, acc);
            }
            float ex[4];
            #pragma unroll
            for (int r = 0; r < 4; r++)
                ex[r] = __shfl_xor_sync(0xffffffffu, acc[r], 1);

            if (epi) {
                __nv_bfloat16* hout = layer ? g_hb[1][(s & 1) ^ 1] : g_hb[0][s & 1];
                {
                    float iv = sigf(acc[0] + add0.x);
                    float fv = sigf(acc[1] + add0.y);
                    float gv = tanh_f(ex[0] + add0.z);
                    float ov = sigf(ex[1] + add0.w);
                    creg0 = fv * creg0 + iv * gv;
                    float h = ov * tanh_f(creg0);
                    __nv_bfloat16 hb = __float2bfloat16(h);
                    hout[b0r * SROW_ + j] = hb;
                    if (layer && sel) g_histb[(size_t)(tstep * B_ + b0r) * NK_ + j] = hb;
                }
                {
                    float iv = sigf(acc[2] + add1.x);
                    float fv = sigf(acc[3] + add1.y);
                    float gv = tanh_f(ex[2] + add1.z);
                    float ov = sigf(ex[3] + add1.w);
                    creg1 = fv * creg1 + iv * gv;
                    float h = ov * tanh_f(creg1);
                    __nv_bfloat16 hb = __float2bfloat16(h);
                    hout[b1r * SROW_ + j] = hb;
                    if (layer && sel) g_histb[(size_t)(tstep * B_ + b1r) * NK_ + j] = hb;
                }
            }
        } else if (layer) {
            mbar_wait(mbarB, s & 1);
        }
        if (s < 128) gbar(s);
    }
}

// ---------------- fused vocab projection + CE: N=128, 512 threads (16 warps) ----------------
// grid 250 blocks x 512 thr. Block tile 128x128; warp = wm(0..3) x wn(0..3): M32 x N32.
// 3-buffer A pipeline, one sync per chunk, cross-tile prefetch.
#define SROWCE_ 536
__global__ __launch_bounds__(512) void ce2(const float* __restrict__ Wout,
                                           const float* __restrict__ bout,
                                           const int* __restrict__ y) {
    extern __shared__ __align__(16) unsigned short csm[];
    unsigned short* sB = csm;                       // [128][SROWCE_] bf16 Wout tile
    unsigned short* sA = csm + 128 * SROWCE_;       // 3 x [128][CROW2_]
    const int tid = threadIdx.x, lane = tid & 31, warp = tid >> 5;
    const int bx = blockIdx.x;

    // ---- load + convert B tile fp32 -> bf16 (once): 128 rows, 4 threads/row ----
    {
        const int r = tid >> 2, qt = tid & 3;
        const int n = bx * 128 + r;
        const float4* src = (const float4*)(Wout + (size_t)n * HID_);
        unsigned short* drow = sB + r * SROWCE_;
        for (int q = qt; q < 129; q += 4) {
            float4 v = src[q];
            ushort4 o;
            o.x = bfc(v.x); o.y = bfc(v.y); o.z = bfc(v.z); o.w = bfc(v.w);
            *(ushort4*)(drow + q * 4) = o;
        }
        if (qt == 0) {   // zero pad cols 516..527
            ushort4 zz = make_ushort4(0, 0, 0, 0);
            *(ushort4*)(drow + 516) = zz;
            *(ushort4*)(drow + 520) = zz;
            *(ushort4*)(drow + 524) = zz;
        }
    }

    const int wm = warp >> 2, wn = warp & 3;
    const unsigned sbA = smem_u32(sA);
    const unsigned bufB = (unsigned)128 * CROW2_ * 2;
    const unsigned a_off =
        (((unsigned)((lane & 7) + ((lane >> 3) & 1) * 8)) * CROW2_ + (unsigned)(lane >> 4) * 8) * 2;
    const unsigned short* brow = sB + (wn * 32 + (lane >> 2)) * SROWCE_ + (lane & 3) * 2;

    const int sr = tid >> 2, sh = tid & 3;   // staging: 4 threads/row, 32B each

    // stage chunk C of m-tile MT into buffer BUF (0..2); 512 threads
    #define CSTAGE(MT, C, BUF) do { \
        const size_t srcbase = (size_t)((MT) * 128 + sr) * NK_ + (C) * 64; \
        unsigned dstr = smem_u32(sA) + ((unsigned)(BUF)) * bufB \
                      + (unsigned)(sr * CROW2_) * 2; \
        if ((C) < 8) { \
            const char* s0 = (const char*)(g_histb + srcbase + sh * 16); \
            unsigned d0 = dstr + (unsigned)(sh * 16) * 2; \
            asm volatile("cp.async.cg.shared.global [%0], [%1], 16;" :: "r"(d0), "l"(s0)); \
            asm volatile("cp.async.cg.shared.global [%0], [%1], 16;" :: "r"(d0 + 16), "l"(s0 + 16)); \
        } else if ((sh & 1) == 0) { \
            const char* s0 = (const char*)(g_histb + srcbase + (sh >> 1) * 8); \
            unsigned d0 = dstr + (unsigned)((sh >> 1) * 8) * 2; \
            asm volatile("cp.async.cg.shared.global [%0], [%1], 16;" :: "r"(d0), "l"(s0)); \
        } \
        asm volatile("cp.async.commit_group;"); \
    } while (0)

    __syncthreads();   // sB ready

    CSTAGE(0, 0, 0);
    int buf = 0;

    for (int mt = 0; mt < 16; mt++) {
        float acc[2][4][4];
        #pragma unroll
        for (int a = 0; a < 2; a++) for (int b = 0; b < 4; b++) for (int r = 0; r < 4; r++)
            acc[a][b][r] = 0.f;

        for (int c = 0; c < 9; c++) {
            int nb = buf + 1; if (nb == 3) nb = 0;
            const bool last = (mt == 15) && (c == 8);
            if (!last) {
                if (c < 8) CSTAGE(mt, c + 1, nb);
                else       CSTAGE(mt + 1, 0, nb);
                asm volatile("cp.async.wait_group 1;");
            } else {
                asm volatile("cp.async.wait_group 0;");
            }
            __syncthreads();

            const unsigned chbase = sbA + ((unsigned)buf) * bufB + a_off;
            const int nk16 = (c == 8) ? 1 : 4;
            for (int kk = 0; kk < nk16; kk++) {
                unsigned av[2][4];
                #pragma unroll
                for (int q = 0; q < 2; q++)
                    ldsm4(av[q], chbase + (unsigned)((wm * 32 + q * 16) * CROW2_ + kk * 16) * 2);
                const int k0 = c * 64 + kk * 16;
                #pragma unroll
                for (int nt = 0; nt < 4; nt++) {
                    unsigned b0 = *(const unsigned*)(brow + nt * 8 * SROWCE_ + k0);
                    unsigned b1 = *(const unsigned*)(brow + nt * 8 * SROWCE_ + k0 + 8);
                    #pragma unroll
                    for (int q = 0; q < 2; q++) mma_bf16(acc[q][nt], av[q], b0, b1);
                }
            }
            buf = nb;
        }

        // epilogue for this m-tile
        #pragma unroll
        for (int q = 0; q < 2; q++) {
            const int r0 = mt * 128 + wm * 32 + q * 16 + (lane >> 2);
            const int r1 = r0 + 8;
            const int tg0 = y[r0 + 32];
            const int tg1 = y[r1 + 32];
            float s0 = 0.f, s1 = 0.f;
            #pragma unroll
            for (int nt = 0; nt < 4; nt++) {
                const int cnv = bx * 128 + wn * 32 + nt * 8 + (lane & 3) * 2;
                const float2 bo = *(const float2*)&bout[cnv];
                float l0 = acc[q][nt][0] + bo.x;
                float l1 = acc[q][nt][1] + bo.y;
                float l2 = acc[q][nt][2] + bo.x;
                float l3 = acc[q][nt][3] + bo.y;
                s0 += __expf(l0) + __expf(l1);
                s1 += __expf(l2) + __expf(l3);
                if (cnv == tg0)     atomicAdd(&g_tgt[r0], l0);
                if (cnv + 1 == tg0) atomicAdd(&g_tgt[r0], l1);
                if (cnv == tg1)     atomicAdd(&g_tgt[r1], l2);
                if (cnv + 1 == tg1) atomicAdd(&g_tgt[r1], l3);
            }
            s0 += __shfl_xor_sync(0xffffffffu, s0, 1);
            s0 += __shfl_xor_sync(0xffffffffu, s0, 2);
            s1 += __shfl_xor_sync(0xffffffffu, s1, 1);
            s1 += __shfl_xor_sync(0xffffffffu, s1, 2);
            if (!(lane & 3)) {
                atomicAdd(&g_sumexp[r0], s0);
                atomicAdd(&g_sumexp[r1], s1);
            }
        }
    }
    #undef CSTAGE
}

// ---------------- final reduction ----------------
__global__ __launch_bounds__(256) void finalize_kernel(float* out) {
    __shared__ float sm[256];
    float s = 0.f;
    for (int r = threadIdx.x; r < ROWS_; r += 256)
        s += logf(g_sumexp[r]) - g_tgt[r];
    sm[threadIdx.x] = s;
    __syncthreads();
    for (int st = 128; st; st >>= 1) {
        if (threadIdx.x < st) sm[threadIdx.x] += sm[threadIdx.x + st];
        __syncthreads();
    }
    if (threadIdx.x == 0) out[0] = sm[0] / 32.f;
}

// ---------------- host launcher ----------------
extern "C" void kernel_launch(void* const* d_in, const int* in_sizes, int n_in,
                              void* d_out, int out_size)
{
    (void)in_sizes; (void)n_in; (void)out_size;
    const int*   x        = (const int*)  d_in[0];
    const int*   y        = (const int*)  d_in[1];
    const float* encemb   = (const float*)d_in[2];
    const float* decemb   = (const float*)d_in[3];
    const float* enc_Wih0 = (const float*)d_in[4];
    const float* enc_Whh0 = (const float*)d_in[5];
    const float* enc_bih0 = (const float*)d_in[6];
    const float* enc_bhh0 = (const float*)d_in[7];
    const float* enc_Wih1 = (const float*)d_in[8];
    const float* enc_Whh1 = (const float*)d_in[9];
    const float* enc_bih1 = (const float*)d_in[10];
    const float* enc_bhh1 = (const float*)d_in[11];
    const float* dec_Wih0 = (const float*)d_in[12];
    const float* dec_Whh0 = (const float*)d_in[13];
    const float* dec_bih0 = (const float*)d_in[14];
    const float* dec_bhh0 = (const float*)d_in[15];
    const float* dec_Wih1 = (const float*)d_in[16];
    const float* dec_Whh1 = (const float*)d_in[17];
    const float* dec_bih1 = (const float*)d_in[18];
    const float* dec_bhh1 = (const float*)d_in[19];
    const float* Wout     = (const float*)d_in[20];
    const float* bout     = (const float*)d_in[21];
    float* out = (float*)d_out;

    const int PRE_SMEM  = (128 + 64) * XROW_ * 2;                     // 101,376
    const int SCAN_SMEM = 4 * BUFB_ + 32;                             // 137,248
    const int CE_SMEM   = 128 * SROWCE_ * 2 + 3 * 128 * CROW2_ * 2;   // 192,512
    cudaFuncSetAttribute(pre_gemm,    cudaFuncAttributeMaxDynamicSharedMemorySize, PRE_SMEM);
    cudaFuncSetAttribute(scan_kernel, cudaFuncAttributeMaxDynamicSharedMemorySize, SCAN_SMEM);
    cudaFuncSetAttribute(ce2,         cudaFuncAttributeMaxDynamicSharedMemorySize, CE_SMEM);

    ConvArgs ca;
    ca.w[0] = enc_Whh0; ca.w[1] = enc_Wih1; ca.w[2] = enc_Whh1;
    ca.w[3] = dec_Whh0; ca.w[4] = dec_Wih1; ca.w[5] = dec_Whh1;
    ca.b[0] = enc_bih0; ca.b[1] = enc_bhh0; ca.b[2] = dec_bih0; ca.b[3] = dec_bhh0;
    ca.b[4] = enc_bih1; ca.b[5] = enc_bhh1; ca.b[6] = dec_bih1; ca.b[7] = dec_bhh1;
    const int GC = (NPAD_ * (SROW_ / 2) + 255) / 256;
    conv_setup<<<dim3(GC, 7), 256>>>(ca);                                    // 0

    pre_gemm<<<dim3(33, 32), 256, PRE_SMEM>>>(x, y, encemb, decemb,          // 1
                                              enc_Wih0, dec_Wih0);

    scan_kernel<<<SCANB_, 256, SCAN_SMEM>>>();                               // 2

    ce2<<<250, 512, CE_SMEM>>>(Wout, bout, y);                               // 3  <- ncu sample

    finalize_kernel<<<1, 256>>>(out);                                        // 4
}